// round 4
// baseline (speedup 1.0000x reference)
#include <cuda_runtime.h>
#include <cuda_bf16.h>
#include <limits.h>

#define H_HALF 4096
#define BLOCK 256
#define V4_PER_THREAD 4      // 4 float4 = 16 floats per thread; 256*16 = 4096
#define MAX_HALF_ROWS 8192   // B=4096, two halves per row

__device__ float g_partial[MAX_HALF_ROWS];

__global__ __launch_bounds__(BLOCK)
void pulse_loss_kernel(const float* __restrict__ pred,
                       const float* __restrict__ lab) {
    const long base = (long)blockIdx.x * H_HALF;
    const float4* __restrict__ p4 = (const float4*)(pred + base);
    const float4* __restrict__ l4 = (const float4*)(lab + base);
    const int t = threadIdx.x;

    float sq[V4_PER_THREAD * 4];
    int firstI = INT_MAX;
    int lastI  = -1;

    #pragma unroll
    for (int i = 0; i < V4_PER_THREAD; i++) {
        const int v  = t + i * BLOCK;     // float4 index within half-row (0..1023)
        const int gi = v * 4;             // element index within half-row
        const float4 p = p4[v];
        const float4 l = l4[v];
        float d0 = p.x - l.x, d1 = p.y - l.y, d2 = p.z - l.z, d3 = p.w - l.w;
        sq[i * 4 + 0] = d0 * d0;
        sq[i * 4 + 1] = d1 * d1;
        sq[i * 4 + 2] = d2 * d2;
        sq[i * 4 + 3] = d3 * d3;
        if (fabsf(l.x) > 0.01f) { firstI = min(firstI, gi + 0); lastI = max(lastI, gi + 0); }
        if (fabsf(l.y) > 0.01f) { firstI = min(firstI, gi + 1); lastI = max(lastI, gi + 1); }
        if (fabsf(l.z) > 0.01f) { firstI = min(firstI, gi + 2); lastI = max(lastI, gi + 2); }
        if (fabsf(l.w) > 0.01f) { firstI = min(firstI, gi + 3); lastI = max(lastI, gi + 3); }
    }

    // Block reduce min(firstI), max(lastI)
    __shared__ int s_first[BLOCK / 32];
    __shared__ int s_last[BLOCK / 32];
    __shared__ int s_bcast[2];
    __shared__ float s_sum[BLOCK / 32];

    int wfirst = __reduce_min_sync(0xFFFFFFFFu, firstI);
    int wlast  = __reduce_max_sync(0xFFFFFFFFu, lastI);
    const int wid = t >> 5;
    const int lid = t & 31;
    if (lid == 0) { s_first[wid] = wfirst; s_last[wid] = wlast; }
    __syncthreads();
    if (wid == 0) {
        int f = (lid < BLOCK / 32) ? s_first[lid] : INT_MAX;
        int l = (lid < BLOCK / 32) ? s_last[lid]  : -1;
        f = __reduce_min_sync(0xFFFFFFFFu, f);
        l = __reduce_max_sync(0xFFFFFFFFu, l);
        if (lid == 0) {
            if (f == INT_MAX) { f = 0; l = H_HALF - 1; }  // all-insignificant row: argmax fallback
            s_bcast[0] = f;
            s_bcast[1] = l;
        }
    }
    __syncthreads();
    const int first = s_bcast[0];
    const int last  = s_bcast[1];

    // Weighted sum from register-resident squares
    float acc = 0.0f;
    #pragma unroll
    for (int i = 0; i < V4_PER_THREAD; i++) {
        const int gi = (t + i * BLOCK) * 4;
        #pragma unroll
        for (int j = 0; j < 4; j++) {
            const int e = gi + j;
            const bool outside = (e < first) || (e > last);
            acc += sq[i * 4 + j] * (outside ? 2.0f : 1.0f);
        }
    }

    // Block reduce sum -> deterministic partial per half-row
    #pragma unroll
    for (int o = 16; o > 0; o >>= 1)
        acc += __shfl_xor_sync(0xFFFFFFFFu, acc, o);
    if (lid == 0) s_sum[wid] = acc;
    __syncthreads();
    if (wid == 0) {
        float v = (lid < BLOCK / 32) ? s_sum[lid] : 0.0f;
        #pragma unroll
        for (int o = 16; o > 0; o >>= 1)
            v += __shfl_xor_sync(0xFFFFFFFFu, v, o);
        if (lid == 0)
            g_partial[blockIdx.x] = v;
    }
}

__global__ __launch_bounds__(BLOCK)
void final_reduce_kernel(float* __restrict__ out, int half_rows, float scale) {
    const int t = threadIdx.x;
    float acc = 0.0f;
    // half_rows = 8192 -> 32 elements per thread, fixed order (deterministic)
    for (int i = t; i < half_rows; i += BLOCK)
        acc += g_partial[i];

    __shared__ float s_sum[BLOCK / 32];
    const int wid = t >> 5;
    const int lid = t & 31;
    #pragma unroll
    for (int o = 16; o > 0; o >>= 1)
        acc += __shfl_xor_sync(0xFFFFFFFFu, acc, o);
    if (lid == 0) s_sum[wid] = acc;
    __syncthreads();
    if (wid == 0) {
        float v = (lid < BLOCK / 32) ? s_sum[lid] : 0.0f;
        #pragma unroll
        for (int o = 16; o > 0; o >>= 1)
            v += __shfl_xor_sync(0xFFFFFFFFu, v, o);
        if (lid == 0)
            out[0] = v * scale;
    }
}

extern "C" void kernel_launch(void* const* d_in, const int* in_sizes, int n_in,
                              void* d_out, int out_size) {
    const float* pred = (const float*)d_in[0];
    const float* lab  = (const float*)d_in[1];
    float* out = (float*)d_out;

    const long n = in_sizes[0];          // total elements (B * N)
    const long half_rows = n / H_HALF;   // B * 2
    const long B = half_rows / 2;
    const float scale = 1.0f / ((float)B * (float)H_HALF);

    pulse_loss_kernel<<<(unsigned)half_rows, BLOCK>>>(pred, lab);
    final_reduce_kernel<<<1, BLOCK>>>(out, (int)half_rows, scale);
}

// round 5
// speedup vs baseline: 1.0278x; 1.0278x over previous
#include <cuda_runtime.h>
#include <cuda_bf16.h>
#include <limits.h>

#define H_HALF 4096
#define BLOCK 512
#define V4_PER_THREAD 2      // 2 float4 = 8 floats per thread; 512*8 = 4096
#define NWARP (BLOCK / 32)
#define MAX_HALF_ROWS 8192   // B=4096, two halves per row

__device__ float g_partial[MAX_HALF_ROWS];
__device__ unsigned int g_counter = 0;

__global__ __launch_bounds__(BLOCK)
void pulse_loss_kernel(const float* __restrict__ pred,
                       const float* __restrict__ lab,
                       float* __restrict__ out,
                       float scale) {
    const long base = (long)blockIdx.x * H_HALF;
    const float4* __restrict__ p4 = (const float4*)(pred + base);
    const float4* __restrict__ l4 = (const float4*)(lab + base);
    const int t = threadIdx.x;

    float sq[V4_PER_THREAD * 4];
    int firstI = INT_MAX;
    int lastI  = -1;

    #pragma unroll
    for (int i = 0; i < V4_PER_THREAD; i++) {
        const int v  = t + i * BLOCK;     // float4 index within half-row (0..1023)
        const int gi = v * 4;             // element index within half-row
        const float4 p = __ldcs(&p4[v]);  // streaming: no reuse, evict-first
        const float4 l = __ldcs(&l4[v]);
        float d0 = p.x - l.x, d1 = p.y - l.y, d2 = p.z - l.z, d3 = p.w - l.w;
        sq[i * 4 + 0] = d0 * d0;
        sq[i * 4 + 1] = d1 * d1;
        sq[i * 4 + 2] = d2 * d2;
        sq[i * 4 + 3] = d3 * d3;
        if (fabsf(l.x) > 0.01f) { firstI = min(firstI, gi + 0); lastI = max(lastI, gi + 0); }
        if (fabsf(l.y) > 0.01f) { firstI = min(firstI, gi + 1); lastI = max(lastI, gi + 1); }
        if (fabsf(l.z) > 0.01f) { firstI = min(firstI, gi + 2); lastI = max(lastI, gi + 2); }
        if (fabsf(l.w) > 0.01f) { firstI = min(firstI, gi + 3); lastI = max(lastI, gi + 3); }
    }

    // Block reduce min(firstI), max(lastI)
    __shared__ int s_first[NWARP];
    __shared__ int s_last[NWARP];
    __shared__ int s_bcast[2];
    __shared__ float s_sum[NWARP];
    __shared__ int s_is_last;

    int wfirst = __reduce_min_sync(0xFFFFFFFFu, firstI);
    int wlast  = __reduce_max_sync(0xFFFFFFFFu, lastI);
    const int wid = t >> 5;
    const int lid = t & 31;
    if (lid == 0) { s_first[wid] = wfirst; s_last[wid] = wlast; }
    __syncthreads();
    if (wid == 0) {
        int f = (lid < NWARP) ? s_first[lid] : INT_MAX;
        int l = (lid < NWARP) ? s_last[lid]  : -1;
        f = __reduce_min_sync(0xFFFFFFFFu, f);
        l = __reduce_max_sync(0xFFFFFFFFu, l);
        if (lid == 0) {
            if (f == INT_MAX) { f = 0; l = H_HALF - 1; }  // all-insignificant row: argmax fallback
            s_bcast[0] = f;
            s_bcast[1] = l;
        }
    }
    __syncthreads();
    const int first = s_bcast[0];
    const int last  = s_bcast[1];

    // Weighted sum from register-resident squares
    float acc = 0.0f;
    #pragma unroll
    for (int i = 0; i < V4_PER_THREAD; i++) {
        const int gi = (t + i * BLOCK) * 4;
        #pragma unroll
        for (int j = 0; j < 4; j++) {
            const int e = gi + j;
            const bool outside = (e < first) || (e > last);
            acc += sq[i * 4 + j] * (outside ? 2.0f : 1.0f);
        }
    }

    // Block reduce sum -> deterministic partial per half-row
    #pragma unroll
    for (int o = 16; o > 0; o >>= 1)
        acc += __shfl_xor_sync(0xFFFFFFFFu, acc, o);
    if (lid == 0) s_sum[wid] = acc;
    __syncthreads();
    if (t == 0) {
        float v = 0.0f;
        #pragma unroll
        for (int w = 0; w < NWARP; w++) v += s_sum[w];
        g_partial[blockIdx.x] = v;
        __threadfence();
        unsigned int done = atomicAdd(&g_counter, 1u);
        s_is_last = (done == gridDim.x - 1) ? 1 : 0;
    }
    __syncthreads();

    // Last block: deterministic final reduction over all partials
    if (s_is_last) {
        __threadfence();  // acquire: ensure g_partial writes from all SMs visible
        const int half_rows = gridDim.x;
        float facc = 0.0f;
        for (int i = t; i < half_rows; i += BLOCK)
            facc += __ldcg(&g_partial[i]);   // fixed order per thread -> deterministic

        #pragma unroll
        for (int o = 16; o > 0; o >>= 1)
            facc += __shfl_xor_sync(0xFFFFFFFFu, facc, o);
        if (lid == 0) s_sum[wid] = facc;
        __syncthreads();
        if (t == 0) {
            float v = 0.0f;
            #pragma unroll
            for (int w = 0; w < NWARP; w++) v += s_sum[w];
            out[0] = v * scale;
            g_counter = 0;   // reset for next graph replay
        }
    }
}

extern "C" void kernel_launch(void* const* d_in, const int* in_sizes, int n_in,
                              void* d_out, int out_size) {
    const float* pred = (const float*)d_in[0];
    const float* lab  = (const float*)d_in[1];
    float* out = (float*)d_out;

    const long n = in_sizes[0];          // total elements (B * N)
    const long half_rows = n / H_HALF;   // B * 2
    const long B = half_rows / 2;
    const float scale = 1.0f / ((float)B * (float)H_HALF);

    pulse_loss_kernel<<<(unsigned)half_rows, BLOCK>>>(pred, lab, out, scale);
}

// round 7
// speedup vs baseline: 1.0459x; 1.0177x over previous
#include <cuda_runtime.h>
#include <cuda_bf16.h>
#include <limits.h>

#define H_HALF 4096
#define BLOCK 256
#define V4_PER_THREAD 4      // 4 float4 = 16 floats per thread; 256*16 = 4096
#define NWARP (BLOCK / 32)
#define MAX_HALF_ROWS 8192   // B=4096, two halves per row

__device__ float g_partial[MAX_HALF_ROWS];
__device__ unsigned int g_counter = 0;

__global__ __launch_bounds__(BLOCK)
void pulse_loss_kernel(const float* __restrict__ pred,
                       const float* __restrict__ lab,
                       float* __restrict__ out,
                       float scale) {
    const long base = (long)blockIdx.x * H_HALF;
    const float4* __restrict__ p4 = (const float4*)(pred + base);
    const float4* __restrict__ l4 = (const float4*)(lab + base);
    const int t = threadIdx.x;

    // Issue ALL loads up front (labels first: the block reduce depends only on
    // them; pred loads stay in flight across the barriers).
    float4 l[V4_PER_THREAD];
    float4 p[V4_PER_THREAD];
    #pragma unroll
    for (int i = 0; i < V4_PER_THREAD; i++)
        l[i] = __ldcs(&l4[t + i * BLOCK]);
    #pragma unroll
    for (int i = 0; i < V4_PER_THREAD; i++)
        p[i] = __ldcs(&p4[t + i * BLOCK]);

    // first/last significant index from labels only
    int firstI = INT_MAX;
    int lastI  = -1;
    #pragma unroll
    for (int i = 0; i < V4_PER_THREAD; i++) {
        const int gi = (t + i * BLOCK) * 4;
        if (fabsf(l[i].x) > 0.01f) { firstI = min(firstI, gi + 0); lastI = max(lastI, gi + 0); }
        if (fabsf(l[i].y) > 0.01f) { firstI = min(firstI, gi + 1); lastI = max(lastI, gi + 1); }
        if (fabsf(l[i].z) > 0.01f) { firstI = min(firstI, gi + 2); lastI = max(lastI, gi + 2); }
        if (fabsf(l[i].w) > 0.01f) { firstI = min(firstI, gi + 3); lastI = max(lastI, gi + 3); }
    }

    __shared__ int s_first[NWARP];
    __shared__ int s_last[NWARP];
    __shared__ int s_bcast[2];
    __shared__ float s_sum[NWARP];
    __shared__ int s_is_last;

    int wfirst = __reduce_min_sync(0xFFFFFFFFu, firstI);
    int wlast  = __reduce_max_sync(0xFFFFFFFFu, lastI);
    const int wid = t >> 5;
    const int lid = t & 31;
    if (lid == 0) { s_first[wid] = wfirst; s_last[wid] = wlast; }
    __syncthreads();
    if (wid == 0) {
        int f = (lid < NWARP) ? s_first[lid] : INT_MAX;
        int ll = (lid < NWARP) ? s_last[lid]  : -1;
        f  = __reduce_min_sync(0xFFFFFFFFu, f);
        ll = __reduce_max_sync(0xFFFFFFFFu, ll);
        if (lid == 0) {
            if (f == INT_MAX) { f = 0; ll = H_HALF - 1; }  // all-insignificant: argmax fallback
            s_bcast[0] = f;
            s_bcast[1] = ll;
        }
    }
    __syncthreads();
    const int first = s_bcast[0];
    const int last  = s_bcast[1];

    // Weighted squared diffs (pred loads complete here at the latest)
    float acc = 0.0f;
    #pragma unroll
    for (int i = 0; i < V4_PER_THREAD; i++) {
        const int gi = (t + i * BLOCK) * 4;
        const float d0 = p[i].x - l[i].x;
        const float d1 = p[i].y - l[i].y;
        const float d2 = p[i].z - l[i].z;
        const float d3 = p[i].w - l[i].w;
        const float w0 = (gi + 0 < first || gi + 0 > last) ? 2.0f : 1.0f;
        const float w1 = (gi + 1 < first || gi + 1 > last) ? 2.0f : 1.0f;
        const float w2 = (gi + 2 < first || gi + 2 > last) ? 2.0f : 1.0f;
        const float w3 = (gi + 3 < first || gi + 3 > last) ? 2.0f : 1.0f;
        acc += w0 * d0 * d0 + w1 * d1 * d1 + w2 * d2 * d2 + w3 * d3 * d3;
    }

    // Block reduce sum -> deterministic partial per half-row
    #pragma unroll
    for (int o = 16; o > 0; o >>= 1)
        acc += __shfl_xor_sync(0xFFFFFFFFu, acc, o);
    if (lid == 0) s_sum[wid] = acc;
    __syncthreads();
    if (t == 0) {
        float v = 0.0f;
        #pragma unroll
        for (int w = 0; w < NWARP; w++) v += s_sum[w];
        g_partial[blockIdx.x] = v;
        __threadfence();
        unsigned int done = atomicAdd(&g_counter, 1u);
        s_is_last = (done == gridDim.x - 1) ? 1 : 0;
    }
    __syncthreads();

    // Last block: deterministic final reduction over all partials
    if (s_is_last) {
        __threadfence();  // ensure g_partial writes from all SMs are visible
        const int half_rows = gridDim.x;
        float facc = 0.0f;
        for (int i = t; i < half_rows; i += BLOCK)
            facc += __ldcg(&g_partial[i]);   // fixed order per thread -> deterministic

        #pragma unroll
        for (int o = 16; o > 0; o >>= 1)
            facc += __shfl_xor_sync(0xFFFFFFFFu, facc, o);
        if (lid == 0) s_sum[wid] = facc;
        __syncthreads();
        if (t == 0) {
            float v = 0.0f;
            #pragma unroll
            for (int w = 0; w < NWARP; w++) v += s_sum[w];
            out[0] = v * scale;
            g_counter = 0;   // reset for next graph replay
        }
    }
}

extern "C" void kernel_launch(void* const* d_in, const int* in_sizes, int n_in,
                              void* d_out, int out_size) {
    const float* pred = (const float*)d_in[0];
    const float* lab  = (const float*)d_in[1];
    float* out = (float*)d_out;

    const long n = in_sizes[0];          // total elements (B * N)
    const long half_rows = n / H_HALF;   // B * 2
    const long B = half_rows / 2;
    const float scale = 1.0f / ((float)B * (float)H_HALF);

    pulse_loss_kernel<<<(unsigned)half_rows, BLOCK>>>(pred, lab, out, scale);
}